// round 1
// baseline (speedup 1.0000x reference)
#include <cuda_runtime.h>

// Problem constants
#define B_ 8
#define N_ 2048
#define D_ 128

// Scratch (static __device__ arrays: allocation-free, harness-legal)
__device__ float g_sn[B_ * N_ * D_];     // 8 MB, unnormalized sum_neighbors
__device__ float g_invdeg[B_ * N_];      // 1/degree per (b, row)

// ---------------- packed f32x2 helpers (FFMA2 path) ----------------
__device__ __forceinline__ unsigned long long pk2(float x, float y) {
    unsigned long long r;
    asm("mov.b64 %0, {%1, %2};" : "=l"(r) : "f"(x), "f"(y));
    return r;
}
__device__ __forceinline__ void fma2(unsigned long long& d,
                                     unsigned long long a,
                                     unsigned long long b) {
    asm("fma.rn.f32x2 %0, %1, %2, %0;" : "+l"(d) : "l"(a), "l"(b));
}
__device__ __forceinline__ void upk2(unsigned long long v, float& x, float& y) {
    asm("mov.b64 {%0, %1}, %2;" : "=f"(x), "=f"(y) : "l"(v));
}

// ---------------- degree: 1 warp per cost row, coalesced float4 ----------------
__global__ void __launch_bounds__(256) degree_kernel(const float* __restrict__ cost) {
    int row  = blockIdx.x * 8 + (threadIdx.x >> 5);   // 0 .. B_*N_-1
    int lane = threadIdx.x & 31;
    const float4* r4 = (const float4*)(cost + (size_t)row * N_);
    int cnt = 0;
#pragma unroll
    for (int it = 0; it < 16; ++it) {
        float4 v = r4[it * 32 + lane];
        cnt += (v.x != 0.0f) + (v.y != 0.0f) + (v.z != 0.0f) + (v.w != 0.0f);
    }
#pragma unroll
    for (int off = 16; off > 0; off >>= 1)
        cnt += __shfl_down_sync(0xffffffffu, cnt, off);
    if (lane == 0) g_invdeg[row] = 1.0f / (float)cnt;
}

// ---------------- GEMM1: sn_raw[b,j,d] = sum_i cost[b,i,j] * emb[b,i,d] ----------------
// CTA tile: 128 (j) x 128 (d), KT=16, double-buffered smem, 8x8/thread via f32x2
__global__ void __launch_bounds__(256) gemm1_kernel(const float* __restrict__ cost,
                                                    const float* __restrict__ emb) {
    __shared__ float As[2][16][128];   // cost tile: [k=i][m=j]
    __shared__ float Es[2][16][128];   // emb  tile: [k=i][n=d]

    const int b  = blockIdx.y;
    const int j0 = blockIdx.x * 128;
    const int t  = threadIdx.x;
    const float* costb = cost + (size_t)b * N_ * N_;
    const float* embb  = emb  + (size_t)b * N_ * D_;

    const int tm = (t & 15) * 8;   // j offset within tile
    const int tn = (t >> 4) * 8;   // d offset within tile

    unsigned long long acc[8][4];
#pragma unroll
    for (int m = 0; m < 8; ++m)
#pragma unroll
        for (int p = 0; p < 4; ++p) acc[m][p] = 0ull;

    // cooperative tile load indexing: 512 float4 per tile, 2 per thread
    const int r0a = t >> 5;            // 0..7
    const int r1a = r0a + 8;           // 8..15
    const int ca  = (t & 31) * 4;      // 0..124

    // prologue: load step 0 into buffer 0
    *(float4*)&As[0][r0a][ca] = *(const float4*)(costb + (size_t)r0a * N_ + j0 + ca);
    *(float4*)&As[0][r1a][ca] = *(const float4*)(costb + (size_t)r1a * N_ + j0 + ca);
    *(float4*)&Es[0][r0a][ca] = *(const float4*)(embb + r0a * D_ + ca);
    *(float4*)&Es[0][r1a][ca] = *(const float4*)(embb + r1a * D_ + ca);
    __syncthreads();

#pragma unroll 1
    for (int s = 0; s < 128; ++s) {
        const int buf = s & 1;
        if (s + 1 < 128) {
            const int k0 = (s + 1) * 16;
            *(float4*)&As[buf ^ 1][r0a][ca] =
                *(const float4*)(costb + (size_t)(k0 + r0a) * N_ + j0 + ca);
            *(float4*)&As[buf ^ 1][r1a][ca] =
                *(const float4*)(costb + (size_t)(k0 + r1a) * N_ + j0 + ca);
            *(float4*)&Es[buf ^ 1][r0a][ca] =
                *(const float4*)(embb + (size_t)(k0 + r0a) * D_ + ca);
            *(float4*)&Es[buf ^ 1][r1a][ca] =
                *(const float4*)(embb + (size_t)(k0 + r1a) * D_ + ca);
        }
#pragma unroll
        for (int k = 0; k < 16; ++k) {
            float4 a0 = *(const float4*)&As[buf][k][tm];
            float4 a1 = *(const float4*)&As[buf][k][tm + 4];
            float4 e0 = *(const float4*)&Es[buf][k][tn];
            float4 e1 = *(const float4*)&Es[buf][k][tn + 4];
            unsigned long long ap[8], bp[4];
            ap[0] = pk2(a0.x, a0.x); ap[1] = pk2(a0.y, a0.y);
            ap[2] = pk2(a0.z, a0.z); ap[3] = pk2(a0.w, a0.w);
            ap[4] = pk2(a1.x, a1.x); ap[5] = pk2(a1.y, a1.y);
            ap[6] = pk2(a1.z, a1.z); ap[7] = pk2(a1.w, a1.w);
            bp[0] = pk2(e0.x, e0.y); bp[1] = pk2(e0.z, e0.w);
            bp[2] = pk2(e1.x, e1.y); bp[3] = pk2(e1.z, e1.w);
#pragma unroll
            for (int m = 0; m < 8; ++m)
#pragma unroll
                for (int p = 0; p < 4; ++p) fma2(acc[m][p], ap[m], bp[p]);
        }
        __syncthreads();
    }

    float* snb = g_sn + ((size_t)b * N_ + j0) * D_;
#pragma unroll
    for (int m = 0; m < 8; ++m) {
#pragma unroll
        for (int p = 0; p < 4; ++p) {
            float lo, hi;
            upk2(acc[m][p], lo, hi);
            *(float2*)&snb[(size_t)(tm + m) * D_ + tn + p * 2] = make_float2(lo, hi);
        }
    }
}

// ---------------- GEMM2: out = relu([emb | sn/deg] @ W^T + b) ----------------
// M=128 rows/CTA, N=128 (all d), K=256 in 16 steps. Padded smem stride 132
// (528B, still 16B-aligned per row) to break transpose-store bank conflicts.
#define PAD_ 132
__global__ void __launch_bounds__(256) gemm2_kernel(const float* __restrict__ emb,
                                                    const float* __restrict__ Wp,
                                                    const float* __restrict__ bias,
                                                    float* __restrict__ out) {
    __shared__ float As[2][16][PAD_];   // [k=f][m=row]
    __shared__ float Ws[2][16][PAD_];   // [k=f][n=d]

    const int b  = blockIdx.y;
    const int r0 = blockIdx.x * 128;
    const int t  = threadIdx.x;

    const float* embb = emb     + ((size_t)b * N_ + r0) * D_;
    const float* snb  = g_sn    + ((size_t)b * N_ + r0) * D_;
    const float* idb  = g_invdeg + b * N_ + r0;

    const int tm = (t & 15) * 8;
    const int tn = (t >> 4) * 8;

    unsigned long long acc[8][4];
#pragma unroll
    for (int m = 0; m < 8; ++m)
#pragma unroll
        for (int p = 0; p < 4; ++p) acc[m][p] = 0ull;

    // tile-load indexing: fid in [0,512): m/d = fid>>2, k-offset q = (fid&3)*4
    const int m0 = t >> 2;            // 0..63
    const int m1 = m0 + 64;           // 64..127
    const int q  = (t & 3) * 4;       // 0,4,8,12

#define LOAD_A(BUF, K0, M)                                                        \
    {                                                                             \
        float4 v;                                                                 \
        if ((K0) < 128) {                                                         \
            v = *(const float4*)(embb + (size_t)(M) * D_ + (K0) + q);             \
        } else {                                                                  \
            v = *(const float4*)(snb + (size_t)(M) * D_ + (K0) - 128 + q);        \
            float inv = idb[M];                                                   \
            v.x *= inv; v.y *= inv; v.z *= inv; v.w *= inv;                       \
        }                                                                         \
        As[BUF][q + 0][M] = v.x; As[BUF][q + 1][M] = v.y;                         \
        As[BUF][q + 2][M] = v.z; As[BUF][q + 3][M] = v.w;                         \
    }
#define LOAD_W(BUF, K0, DN)                                                       \
    {                                                                             \
        float4 v = *(const float4*)(Wp + (size_t)(DN) * 256 + (K0) + q);          \
        Ws[BUF][q + 0][DN] = v.x; Ws[BUF][q + 1][DN] = v.y;                       \
        Ws[BUF][q + 2][DN] = v.z; Ws[BUF][q + 3][DN] = v.w;                       \
    }

    LOAD_A(0, 0, m0); LOAD_A(0, 0, m1);
    LOAD_W(0, 0, m0); LOAD_W(0, 0, m1);
    __syncthreads();

#pragma unroll 1
    for (int s = 0; s < 16; ++s) {
        const int buf = s & 1;
        if (s + 1 < 16) {
            const int k0 = (s + 1) * 16;
            LOAD_A(buf ^ 1, k0, m0); LOAD_A(buf ^ 1, k0, m1);
            LOAD_W(buf ^ 1, k0, m0); LOAD_W(buf ^ 1, k0, m1);
        }
#pragma unroll
        for (int k = 0; k < 16; ++k) {
            float4 a0 = *(const float4*)&As[buf][k][tm];
            float4 a1 = *(const float4*)&As[buf][k][tm + 4];
            float4 w0 = *(const float4*)&Ws[buf][k][tn];
            float4 w1 = *(const float4*)&Ws[buf][k][tn + 4];
            unsigned long long ap[8], bp[4];
            ap[0] = pk2(a0.x, a0.x); ap[1] = pk2(a0.y, a0.y);
            ap[2] = pk2(a0.z, a0.z); ap[3] = pk2(a0.w, a0.w);
            ap[4] = pk2(a1.x, a1.x); ap[5] = pk2(a1.y, a1.y);
            ap[6] = pk2(a1.z, a1.z); ap[7] = pk2(a1.w, a1.w);
            bp[0] = pk2(w0.x, w0.y); bp[1] = pk2(w0.z, w0.w);
            bp[2] = pk2(w1.x, w1.y); bp[3] = pk2(w1.z, w1.w);
#pragma unroll
            for (int m = 0; m < 8; ++m)
#pragma unroll
                for (int p = 0; p < 4; ++p) fma2(acc[m][p], ap[m], bp[p]);
        }
        __syncthreads();
    }

    float bv[8];
#pragma unroll
    for (int i = 0; i < 8; ++i) bv[i] = bias[tn + i];

    float* outb = out + ((size_t)b * N_ + r0) * D_;
#pragma unroll
    for (int m = 0; m < 8; ++m) {
#pragma unroll
        for (int p = 0; p < 4; ++p) {
            float lo, hi;
            upk2(acc[m][p], lo, hi);
            lo = fmaxf(lo + bv[p * 2], 0.0f);
            hi = fmaxf(hi + bv[p * 2 + 1], 0.0f);
            *(float2*)&outb[(size_t)(tm + m) * D_ + tn + p * 2] = make_float2(lo, hi);
        }
    }
}

// ---------------- launch ----------------
extern "C" void kernel_launch(void* const* d_in, const int* in_sizes, int n_in,
                              void* d_out, int out_size) {
    const float* emb  = (const float*)d_in[0];   // [8, 2048, 128]
    const float* cost = (const float*)d_in[1];   // [8, 2048, 2048]
    const float* W    = (const float*)d_in[2];   // [128, 256]
    const float* bias = (const float*)d_in[3];   // [128]
    float* out = (float*)d_out;                  // [8, 2048, 128]

    degree_kernel<<<(B_ * N_) / 8, 256>>>(cost);

    dim3 grid(N_ / 128, B_);
    gemm1_kernel<<<grid, 256>>>(cost, emb);
    gemm2_kernel<<<grid, 256>>>(emb, W, bias, out);
}

// round 3
// speedup vs baseline: 3.1274x; 3.1274x over previous
#include <cuda_runtime.h>
#include <cuda_bf16.h>
#include <cstdint>

#define B_ 8
#define N_ 2048
#define D_ 128

// ---------------- scratch (__device__ globals: allocation-free) ----------------
__device__ __align__(16) unsigned int g_costb16[(size_t)B_ * N_ * N_ / 2]; // bf16 [b][i][j]
__device__ __align__(16) unsigned int g_embT[(size_t)B_ * D_ * N_ / 2];    // bf16 [b][d][i]
__device__ __align__(16) float g_snT[(size_t)B_ * D_ * N_];                // fp32 [b][d][j]
__device__ float g_invdeg[B_ * N_];

// ---------------- helpers ----------------
__device__ __forceinline__ uint32_t smem_to_u32(const void* p) {
    uint32_t a;
    asm("{ .reg .u64 t; cvta.to.shared.u64 t, %1; cvt.u32.u64 %0, t; }" : "=r"(a) : "l"(p));
    return a;
}
#define CPA16(dst, src) \
    asm volatile("cp.async.cg.shared.global [%0], [%1], 16;" :: "r"(dst), "l"(src) : "memory")
#define CP_COMMIT() asm volatile("cp.async.commit_group;" ::: "memory")
#define CP_WAIT(n)  asm volatile("cp.async.wait_group %0;" :: "n"(n) : "memory")

#define LDSM4(r, addr) \
    asm volatile("ldmatrix.sync.aligned.m8n8.x4.shared.b16 {%0,%1,%2,%3}, [%4];" \
                 : "=r"((r)[0]), "=r"((r)[1]), "=r"((r)[2]), "=r"((r)[3]) : "r"(addr))
#define LDSM4T(r, addr) \
    asm volatile("ldmatrix.sync.aligned.m8n8.x4.trans.shared.b16 {%0,%1,%2,%3}, [%4];" \
                 : "=r"((r)[0]), "=r"((r)[1]), "=r"((r)[2]), "=r"((r)[3]) : "r"(addr))
#define MMA16816(c, a, b0, b1) \
    asm volatile("mma.sync.aligned.m16n8k16.row.col.f32.bf16.bf16.f32 " \
                 "{%0,%1,%2,%3}, {%4,%5,%6,%7}, {%8,%9}, {%0,%1,%2,%3};" \
                 : "+f"((c)[0]), "+f"((c)[1]), "+f"((c)[2]), "+f"((c)[3]) \
                 : "r"((a)[0]), "r"((a)[1]), "r"((a)[2]), "r"((a)[3]), "r"(b0), "r"(b1))

// ---------------- degree + fp32->bf16 cost conversion (fused single pass) ----------------
__global__ void __launch_bounds__(256) degconv_kernel(const float* __restrict__ cost) {
    int row  = blockIdx.x * 8 + (threadIdx.x >> 5);
    int lane = threadIdx.x & 31;
    const float4* r4 = (const float4*)(cost + (size_t)row * N_);
    unsigned int* w = g_costb16 + (size_t)row * (N_ / 2);
    int cnt = 0;
#pragma unroll
    for (int it = 0; it < 16; ++it) {
        float4 v = r4[it * 32 + lane];
        cnt += (v.x != 0.0f) + (v.y != 0.0f) + (v.z != 0.0f) + (v.w != 0.0f);
        unsigned int p0, p1;
        asm("cvt.rn.satfinite.bf16x2.f32 %0, %1, %2;" : "=r"(p0) : "f"(v.y), "f"(v.x));
        asm("cvt.rn.satfinite.bf16x2.f32 %0, %1, %2;" : "=r"(p1) : "f"(v.w), "f"(v.z));
        *(uint2*)&w[it * 64 + lane * 2] = make_uint2(p0, p1);
    }
#pragma unroll
    for (int off = 16; off > 0; off >>= 1)
        cnt += __shfl_down_sync(0xffffffffu, cnt, off);
    if (lane == 0) g_invdeg[row] = 1.0f / (float)cnt;
}

// ---------------- emb -> embT bf16 transpose: [b][i][d] -> [b][d][i] ----------------
__global__ void __launch_bounds__(256) embT_kernel(const float* __restrict__ emb) {
    __shared__ float tile[32][33];
    int b = blockIdx.z, i0 = blockIdx.x * 32, d0 = blockIdx.y * 32;
    int tx = threadIdx.x & 31, ty = threadIdx.x >> 5;
    const float* src = emb + ((size_t)b * N_ + i0) * D_ + d0;
#pragma unroll
    for (int k = 0; k < 4; ++k)
        tile[ty + 8 * k][tx] = src[(ty + 8 * k) * D_ + tx];
    __syncthreads();
    __nv_bfloat16* dst = (__nv_bfloat16*)g_embT + ((size_t)b * D_ + d0) * N_ + i0;
#pragma unroll
    for (int k = 0; k < 4; ++k)
        dst[(ty + 8 * k) * N_ + tx] = __float2bfloat16(tile[tx][ty + 8 * k]);
}

// ---------------- GEMM1 (mma.sync bf16): snT[b][d][j] = sum_i cost[b,i,j]*emb[b,i,d] ----------------
// CTA 128(d=M) x 128(j=N); 4 warps of 64x64 (2x2); K=i streamed in 64-wide
// double-buffered cp.async stages. A tile [128][64] bf16 (128B rows, SW128),
// B tile [64][128] bf16 (256B rows, SW swizzle within row).
#define G1_STAGE 32768   // A 16KB + B 16KB

__device__ __forceinline__ void g1_load(uint32_t sb, int st,
                                        const __nv_bfloat16* __restrict__ costb,
                                        const __nv_bfloat16* __restrict__ embTb,
                                        int i0, int j0, int t) {
    uint32_t abase = sb + st * G1_STAGE;
    uint32_t bbase = abase + 16384;
#pragma unroll
    for (int p = 0; p < 8; ++p) {           // A: 128 rows x 8 x 16B
        int ca = t + p * 128;
        int row = ca >> 3, c = ca & 7;
        uint32_t dst = abase + row * 128 + ((c * 16) ^ ((row & 7) << 4));
        CPA16(dst, embTb + (size_t)row * N_ + i0 + c * 8);
    }
#pragma unroll
    for (int p = 0; p < 8; ++p) {           // B: 64 rows x 16 x 16B
        int cb = t + p * 128;
        int row = cb >> 4, jc = cb & 15;
        uint32_t dst = bbase + row * 256 + ((jc * 16) ^ ((row & 7) << 4));
        CPA16(dst, costb + (size_t)(i0 + row) * N_ + j0 + jc * 8);
    }
}

__global__ void __launch_bounds__(128) gemm1_mma_kernel() {
    extern __shared__ char smem[];
    uint32_t sb = smem_to_u32(smem);
    const int t = threadIdx.x, wid = t >> 5, l = t & 31;
    const int b = blockIdx.y, j0 = blockIdx.x * 128;
    const __nv_bfloat16* costb = (const __nv_bfloat16*)g_costb16 + (size_t)b * N_ * N_;
    const __nv_bfloat16* embTb = (const __nv_bfloat16*)g_embT + (size_t)b * D_ * N_;

    const int wm = (wid & 1) * 64;          // d offset of warp
    const int wn = (wid >> 1) * 64;         // j offset of warp
    const int lq = l & 15, lh = l >> 4;
    const uint32_t sx = (uint32_t)(l & 7) << 4;

    float acc[4][8][4];
#pragma unroll
    for (int mt = 0; mt < 4; ++mt)
#pragma unroll
        for (int n8 = 0; n8 < 8; ++n8)
#pragma unroll
            for (int r = 0; r < 4; ++r) acc[mt][n8][r] = 0.0f;

    g1_load(sb, 0, costb, embTb, 0, j0, t);
    CP_COMMIT();

#pragma unroll 1
    for (int c = 0; c < 32; ++c) {
        if (c + 1 < 32) {
            g1_load(sb, (c + 1) & 1, costb, embTb, (c + 1) * 64, j0, t);
            CP_COMMIT();
            CP_WAIT(1);
        } else {
            CP_WAIT(0);
        }
        __syncthreads();

        uint32_t abase = sb + (c & 1) * G1_STAGE;
        uint32_t bbase = abase + 16384;
#pragma unroll
        for (int ks = 0; ks < 4; ++ks) {
            uint32_t a[4][4], bf[4][4];
#pragma unroll
            for (int mt = 0; mt < 4; ++mt) {
                uint32_t addr = abase + (uint32_t)(wm + mt * 16 + lq) * 128 +
                                (((uint32_t)(ks * 32 + lh * 16)) ^ sx);
                LDSM4(a[mt], addr);
            }
#pragma unroll
            for (int nt = 0; nt < 4; ++nt) {
                uint32_t addr = bbase + (uint32_t)(ks * 16 + lq) * 256 +
                                (((uint32_t)((wn + nt * 16 + lh * 8) * 2)) ^ sx);
                LDSM4T(bf[nt], addr);
            }
#pragma unroll
            for (int mt = 0; mt < 4; ++mt)
#pragma unroll
                for (int nt = 0; nt < 4; ++nt) {
                    MMA16816(acc[mt][2 * nt],     a[mt], bf[nt][0], bf[nt][1]);
                    MMA16816(acc[mt][2 * nt + 1], a[mt], bf[nt][2], bf[nt][3]);
                }
        }
        __syncthreads();
    }

    // epilogue: acc -> g_snT[b][d][j]
    float* dstb = g_snT + (size_t)b * D_ * N_;
    const int mrow = wm + (l >> 2);
    const int jcol = j0 + wn + (l & 3) * 2;
#pragma unroll
    for (int mt = 0; mt < 4; ++mt) {
#pragma unroll
        for (int n8 = 0; n8 < 8; ++n8) {
            int m = mrow + mt * 16;
            int j = jcol + n8 * 8;
            *(float2*)&dstb[(size_t)m * N_ + j] =
                make_float2(acc[mt][n8][0], acc[mt][n8][1]);
            *(float2*)&dstb[(size_t)(m + 8) * N_ + j] =
                make_float2(acc[mt][n8][2], acc[mt][n8][3]);
        }
    }
}

// ---------------- packed f32x2 helpers (FFMA2, for GEMM2) ----------------
__device__ __forceinline__ unsigned long long pk2(float x, float y) {
    unsigned long long r;
    asm("mov.b64 %0, {%1, %2};" : "=l"(r) : "f"(x), "f"(y));
    return r;
}
__device__ __forceinline__ void fma2(unsigned long long& d, unsigned long long a,
                                     unsigned long long b) {
    asm("fma.rn.f32x2 %0, %1, %2, %0;" : "+l"(d) : "l"(a), "l"(b));
}
__device__ __forceinline__ void upk2(unsigned long long v, float& x, float& y) {
    asm("mov.b64 {%0, %1}, %2;" : "=f"(x), "=f"(y) : "l"(v));
}

// ---------------- GEMM2: out = relu([emb | snT/deg] @ W^T + b) ----------------
#define PAD_ 132
__global__ void __launch_bounds__(256) gemm2_kernel(const float* __restrict__ emb,
                                                    const float* __restrict__ Wp,
                                                    const float* __restrict__ bias,
                                                    float* __restrict__ out) {
    __shared__ float As[2][16][PAD_];
    __shared__ float Ws[2][16][PAD_];
    __shared__ float invs[128];

    const int b  = blockIdx.y;
    const int r0 = blockIdx.x * 128;
    const int t  = threadIdx.x;

    const float* embb = emb + ((size_t)b * N_ + r0) * D_;

    const int tm = (t & 15) * 8;
    const int tn = (t >> 4) * 8;

    unsigned long long acc[8][4];
#pragma unroll
    for (int m = 0; m < 8; ++m)
#pragma unroll
        for (int p = 0; p < 4; ++p) acc[m][p] = 0ull;

    const int m0 = t >> 2;
    const int m1 = m0 + 64;
    const int q  = (t & 3) * 4;

    if (t < 128) invs[t] = g_invdeg[b * N_ + r0 + t];

#define LOAD_EMB(BUF, K0, M)                                                      \
    {                                                                             \
        float4 v = *(const float4*)(embb + (size_t)(M) * D_ + (K0) + q);          \
        As[BUF][q + 0][M] = v.x; As[BUF][q + 1][M] = v.y;                         \
        As[BUF][q + 2][M] = v.z; As[BUF][q + 3][M] = v.w;                         \
    }
#define LOAD_SN(BUF, K0)                                                          \
    {                                                                             \
        int kk = t >> 4, mm = (t & 15) * 8;                                       \
        const float* srow = g_snT + ((size_t)b * D_ + ((K0) - 128 + kk)) * N_ + r0; \
        float4 v0 = *(const float4*)&srow[mm];                                    \
        float4 v1 = *(const float4*)&srow[mm + 4];                                \
        v0.x *= invs[mm + 0]; v0.y *= invs[mm + 1];                               \
        v0.z *= invs[mm + 2]; v0.w *= invs[mm + 3];                               \
        v1.x *= invs[mm + 4]; v1.y *= invs[mm + 5];                               \
        v1.z *= invs[mm + 6]; v1.w *= invs[mm + 7];                               \
        *(float4*)&As[BUF][kk][mm]     = v0;                                      \
        *(float4*)&As[BUF][kk][mm + 4] = v1;                                      \
    }
#define LOAD_W(BUF, K0, DN)                                                       \
    {                                                                             \
        float4 v = *(const float4*)(Wp + (size_t)(DN) * 256 + (K0) + q);          \
        Ws[BUF][q + 0][DN] = v.x; Ws[BUF][q + 1][DN] = v.y;                       \
        Ws[BUF][q + 2][DN] = v.z; Ws[BUF][q + 3][DN] = v.w;                       \
    }
#define LOAD_STAGE(BUF, K0)                                                       \
    {                                                                             \
        if ((K0) < 128) { LOAD_EMB(BUF, K0, m0); LOAD_EMB(BUF, K0, m1); }         \
        else            { LOAD_SN(BUF, K0); }                                     \
        LOAD_W(BUF, K0, m0); LOAD_W(BUF, K0, m1);                                 \
    }

    LOAD_STAGE(0, 0);
    __syncthreads();

#pragma unroll 1
    for (int s = 0; s < 16; ++s) {
        const int buf = s & 1;
        if (s + 1 < 16) {
            const int k0 = (s + 1) * 16;
            LOAD_STAGE(buf ^ 1, k0);
        }
#pragma unroll
        for (int k = 0; k < 16; ++k) {
            float4 a0 = *(const float4*)&As[buf][k][tm];
            float4 a1 = *(const float4*)&As[buf][k][tm + 4];
            float4 w0 = *(const float4*)&Ws[buf][k][tn];
            float4 w1 = *(const float4*)&Ws[buf][k][tn + 4];
            unsigned long long ap[8], bp[4];
            ap[0] = pk2(a0.x, a0.x); ap[1] = pk2(a0.y, a0.y);
            ap[2] = pk2(a0.z, a0.z); ap[3] = pk2(a0.w, a0.w);
            ap[4] = pk2(a1.x, a1.x); ap[5] = pk2(a1.y, a1.y);
            ap[6] = pk2(a1.z, a1.z); ap[7] = pk2(a1.w, a1.w);
            bp[0] = pk2(w0.x, w0.y); bp[1] = pk2(w0.z, w0.w);
            bp[2] = pk2(w1.x, w1.y); bp[3] = pk2(w1.z, w1.w);
#pragma unroll
            for (int m = 0; m < 8; ++m)
#pragma unroll
                for (int p = 0; p < 4; ++p) fma2(acc[m][p], ap[m], bp[p]);
        }
        __syncthreads();
    }

    float bv[8];
#pragma unroll
    for (int i = 0; i < 8; ++i) bv[i] = bias[tn + i];

    float* outb = out + ((size_t)b * N_ + r0) * D_;
#pragma unroll
    for (int m = 0; m < 8; ++m) {
#pragma unroll
        for (int p = 0; p < 4; ++p) {
            float lo, hi;
            upk2(acc[m][p], lo, hi);
            lo = fmaxf(lo + bv[p * 2], 0.0f);
            hi = fmaxf(hi + bv[p * 2 + 1], 0.0f);
            *(float2*)&outb[(size_t)(tm + m) * D_ + tn + p * 2] = make_float2(lo, hi);
        }
    }
}

// ---------------- launch ----------------
extern "C" void kernel_launch(void* const* d_in, const int* in_sizes, int n_in,
                              void* d_out, int out_size) {
    const float* emb  = (const float*)d_in[0];   // [8, 2048, 128]
    const float* cost = (const float*)d_in[1];   // [8, 2048, 2048]
    const float* W    = (const float*)d_in[2];   // [128, 256]
    const float* bias = (const float*)d_in[3];   // [128]
    float* out = (float*)d_out;                  // [8, 2048, 128]

    degconv_kernel<<<(B_ * N_) / 8, 256>>>(cost);
    embT_kernel<<<dim3(N_ / 32, D_ / 32, B_), 256>>>(emb);

    cudaFuncSetAttribute(gemm1_mma_kernel,
                         cudaFuncAttributeMaxDynamicSharedMemorySize, 2 * G1_STAGE);
    gemm1_mma_kernel<<<dim3(N_ / 128, B_), 128, 2 * G1_STAGE>>>();

    gemm2_kernel<<<dim3(N_ / 128, B_), 256>>>(emb, W, bias, out);
}